// round 5
// baseline (speedup 1.0000x reference)
#include <cuda_runtime.h>

#define Bn 64
#define Mn 200
#define Sn 50
#define Qn 20
#define Dn 128
#define Vn 50000
#define HOPSn 3
#define NEG_INF -1e9f

typedef unsigned long long ull;

// ---- packed fp32x2 helpers (sm_103a FFMA2 via PTX) ----
__device__ __forceinline__ ull pack2(float lo, float hi) {
    ull r; asm("mov.b64 %0, {%1, %2};" : "=l"(r) : "f"(lo), "f"(hi)); return r;
}
__device__ __forceinline__ float2 unpack2(ull v) {
    float2 f; asm("mov.b64 {%0, %1}, %2;" : "=f"(f.x), "=f"(f.y) : "l"(v)); return f;
}
__device__ __forceinline__ ull fma2(ull a, ull b, ull c) {
    ull d; asm("fma.rn.f32x2 %0, %1, %2, %3;" : "=l"(d) : "l"(a), "l"(b), "l"(c)); return d;
}

// Scratch (static __device__ globals: allowed; no runtime allocation)
__device__ float g_emb[4][Bn * Mn][Dn];   // embeddings of A0, C0, C1, C2  (~26 MB)
__device__ float g_u[Bn][Dn];             // controller state after hops
__device__ int   g_nonpad[Bn * Mn];       // mem_nonpad mask

// ---------------------------------------------------------------------------
// Kernel 1: story embedding gather, FFMA2 version.
//  grid = (Bn*Mn, 4): y = table (phase locality in L2, proven R4).
//  Rows loaded as ulonglong2 (reg pairs = packed f32x2 operands, no pack cost).
//  Packed PE weights (a,a),(b,b) precomputed in smem.
//  Per row: 4 FFMA2 + 3 broadcast LDS + 1 LDG.128  (~9 instrs vs ~16).
// ---------------------------------------------------------------------------
__global__ void __launch_bounds__(128) embed_story_kernel(
    const int* __restrict__ story,
    const float* __restrict__ T0, const float* __restrict__ T1,
    const float* __restrict__ T2, const float* __restrict__ T3)
{
    __shared__ int    idx[Sn];
    __shared__ ull    wa2[Sn], wb2[Sn];
    __shared__ float4 part[4][32];
    const int bm   = blockIdx.x;
    const int tb   = blockIdx.y;
    const int t    = threadIdx.x;
    const int warp = t >> 5;
    const int lane = t & 31;

    if (t < Sn) {
        int w = story[bm * Sn + t];
        idx[t] = w;
        float j  = (float)(t + 1);
        float a  = 1.0f - j * (1.0f / Sn);
        float bb = 2.0f * j * (1.0f / Sn) - 1.0f;
        wa2[t] = pack2(a, a);
        wb2[t] = pack2(bb, bb);
    }
    __syncthreads();
    if (tb == 0) {
        int np = __syncthreads_or((t < Sn) && (idx[t] != 0));
        if (t == 0) g_nonpad[bm] = np;
    }

    const ulonglong2* tab = (const ulonglong2*)(tb == 0 ? T0 : tb == 1 ? T1
                                                : tb == 2 ? T2 : T3);
    const float cb = (float)(4 * lane) * (1.0f / Dn);
    const ull cxy = pack2(cb + 1.0f / Dn, cb + 2.0f / Dn);
    const ull czw = pack2(cb + 3.0f / Dn, cb + 4.0f / Dn);

    ull accxy = 0ull, acczw = 0ull;
    const int start = (Sn * warp) >> 2;        // {0,12,25,37}
    const int end   = (Sn * (warp + 1)) >> 2;  // {12,25,37,50}
    int s = start;
    for (; s + 4 <= end; s += 4) {
        int w0 = idx[s], w1 = idx[s + 1], w2i = idx[s + 2], w3 = idx[s + 3];
        ulonglong2 r0 = tab[w0  * 32 + lane];
        ulonglong2 r1 = tab[w1  * 32 + lane];
        ulonglong2 r2 = tab[w2i * 32 + lane];
        ulonglong2 r3 = tab[w3  * 32 + lane];
        accxy = fma2(fma2(wb2[s    ], cxy, wa2[s    ]), r0.x, accxy);
        acczw = fma2(fma2(wb2[s    ], czw, wa2[s    ]), r0.y, acczw);
        accxy = fma2(fma2(wb2[s + 1], cxy, wa2[s + 1]), r1.x, accxy);
        acczw = fma2(fma2(wb2[s + 1], czw, wa2[s + 1]), r1.y, acczw);
        accxy = fma2(fma2(wb2[s + 2], cxy, wa2[s + 2]), r2.x, accxy);
        acczw = fma2(fma2(wb2[s + 2], czw, wa2[s + 2]), r2.y, acczw);
        accxy = fma2(fma2(wb2[s + 3], cxy, wa2[s + 3]), r3.x, accxy);
        acczw = fma2(fma2(wb2[s + 3], czw, wa2[s + 3]), r3.y, acczw);
    }
    for (; s < end; s++) {
        ulonglong2 r = tab[idx[s] * 32 + lane];
        accxy = fma2(fma2(wb2[s], cxy, wa2[s]), r.x, accxy);
        acczw = fma2(fma2(wb2[s], czw, wa2[s]), r.y, acczw);
    }
    float2 axy = unpack2(accxy), azw = unpack2(acczw);
    part[warp][lane] = make_float4(axy.x, axy.y, azw.x, azw.y);
    __syncthreads();
    if (warp == 0) {
        float4 a0 = part[0][lane], a1 = part[1][lane];
        float4 a2 = part[2][lane], a3 = part[3][lane];
        float4 r;
        r.x = (a0.x + a1.x) + (a2.x + a3.x);
        r.y = (a0.y + a1.y) + (a2.y + a3.y);
        r.z = (a0.z + a1.z) + (a2.z + a3.z);
        r.w = (a0.w + a1.w) + (a2.w + a3.w);
        ((float4*)g_emb[tb][bm])[lane] = r;
    }
}

// ---------------------------------------------------------------------------
// Kernel 2: query embed + 3 hops, 1024 threads per batch b.
//  Score loop: 6 unconditional fully-unrolled iters + 1 guarded (MLP 6).
//  Softmax: single warp, 2 barriers instead of 4.
// ---------------------------------------------------------------------------
__global__ void __launch_bounds__(1024) hops_kernel(
    const int* __restrict__ question, const float* __restrict__ Bemb,
    const float* __restrict__ TA, const float* __restrict__ TC)
{
    __shared__ float u_sh[Dn];
    __shared__ float sc[Mn];
    __shared__ float scp[Mn][33];        // padded: conflict-free transpose
    __shared__ float partial[8][Dn];
    __shared__ float s_sum;
    __shared__ int   qidx[Qn];
    __shared__ float qa[Qn], qb[Qn];

    const int b    = blockIdx.x;
    const int t    = threadIdx.x;
    const int warp = t >> 5;
    const int lane = t & 31;

    // ---- query embedding u^1 ----
    if (t < Qn) {
        int w = question[b * Qn + t];
        qidx[t] = w;
        float j = (float)(t + 1);
        qa[t] = 1.0f - j * (1.0f / Qn);
        qb[t] = 2.0f * j * (1.0f / Qn) - 1.0f;
    }
    __syncthreads();
    if (t < Dn) {
        const float cd = (float)(t + 1) * (1.0f / Dn);
        float acc = 0.f;
#pragma unroll
        for (int q = 0; q < Qn; q++) {
            float wgt = fmaf(qb[q], cd, qa[q]);
            acc = fmaf(wgt, Bemb[qidx[q] * Dn + t], acc);
        }
        u_sh[t] = acc;
    }
    __syncthreads();

    for (int k = 0; k < HOPSn; k++) {
        const float4* embA = (const float4*)g_emb[k];
        const float*  embC = (const float*)g_emb[k + 1];

        // ---- per-lane score partials: warp covers m = warp + 32*i ----
        float4 uu = ((const float4*)u_sh)[lane];
#pragma unroll
        for (int i = 0; i < 6; i++) {
            int m = warp + 32 * i;                       // always < 200
            float4 e  = embA[(b * Mn + m) * (Dn / 4) + lane];
            float4 ta = ((const float4*)TA)[m * (Dn / 4) + lane];
            scp[m][lane] = (e.x + ta.x) * uu.x + (e.y + ta.y) * uu.y
                         + (e.z + ta.z) * uu.z + (e.w + ta.w) * uu.w;
        }
        {
            int m = warp + 192;
            if (m < Mn) {
                float4 e  = embA[(b * Mn + m) * (Dn / 4) + lane];
                float4 ta = ((const float4*)TA)[m * (Dn / 4) + lane];
                scp[m][lane] = (e.x + ta.x) * uu.x + (e.y + ta.y) * uu.y
                             + (e.z + ta.z) * uu.z + (e.w + ta.w) * uu.w;
            }
        }
        __syncthreads();

        // ---- reduce 32 partials per m, write raw masked score ----
        if (t < Mn) {
            float p0 = 0.f, p1 = 0.f, p2 = 0.f, p3 = 0.f;
#pragma unroll
            for (int i = 0; i < 32; i += 4) {
                p0 += scp[t][i];
                p1 += scp[t][i + 1];
                p2 += scp[t][i + 2];
                p3 += scp[t][i + 3];
            }
            float p = (p0 + p1) + (p2 + p3);
            sc[t] = g_nonpad[b * Mn + t] ? p : NEG_INF;
        }
        __syncthreads();

        // ---- softmax over M=200 in ONE warp ----
        if (warp == 0) {
            float v[7];
            float lm = -3e38f;
#pragma unroll
            for (int i = 0; i < 7; i++) {
                int m = lane + 32 * i;
                v[i] = (m < Mn) ? sc[m] : -3e38f;
                lm = fmaxf(lm, v[i]);
            }
#pragma unroll
            for (int off = 16; off; off >>= 1)
                lm = fmaxf(lm, __shfl_xor_sync(0xffffffffu, lm, off));
            float ls = 0.f;
#pragma unroll
            for (int i = 0; i < 7; i++) {
                int m = lane + 32 * i;
                if (m < Mn) {
                    float e = __expf(v[i] - lm);
                    sc[m] = e;
                    ls += e;
                }
            }
#pragma unroll
            for (int off = 16; off; off >>= 1)
                ls += __shfl_xor_sync(0xffffffffu, ls, off);
            if (lane == 0) s_sum = ls;
        }
        __syncthreads();
        const float inv = 1.0f / s_sum;

        // ---- o[d] = sum_m p[m]*(c_k[m,d]+TC[m,d]) : 8 groups x 128 ----
        const int g = t >> 7;     // group 0..7
        const int d = t & 127;    // dim
        float o = 0.f;
#pragma unroll
        for (int mi = 0; mi < Mn / 8; mi++) {
            int m = g + mi * 8;
            float c = embC[(b * Mn + m) * Dn + d] + TC[m * Dn + d];
            o = fmaf(sc[m], c, o);
        }
        partial[g][d] = o;
        __syncthreads();
        if (t < Dn) {
            float s2 = 0.f;
#pragma unroll
            for (int g2 = 0; g2 < 8; g2++) s2 += partial[g2][t];
            u_sh[t] += s2 * inv;
        }
        __syncthreads();
    }
    if (t < Dn) g_u[b][t] = u_sh[t];
}

// ---------------------------------------------------------------------------
// Kernel 3: logits = u @ W^T + bias, FFMA2 version.
//  grid.y = batch half (32 b's per block -> acc2[32] packed even/odd-d sums).
//  Per (d4, 32b): 32 broadcast LDS.128 + 64 FFMA2 (was 64 LDS + 256 FFMA/64b).
// ---------------------------------------------------------------------------
__global__ void __launch_bounds__(128) logits_kernel(
    const float* __restrict__ W, const float* __restrict__ bias,
    float* __restrict__ out)
{
    __shared__ ulonglong2 u_sh[32 * 32];   // 32 b x 32 d4 = 16 KB
    const int t  = threadIdx.x;
    const int bh = blockIdx.y;             // batch half: 0 or 1
    const float4* gu4 = ((const float4*)g_u) + bh * (32 * (Dn / 4));
#pragma unroll
    for (int i = 0; i < 8; i++)
        ((float4*)u_sh)[t + i * 128] = gu4[t + i * 128];
    __syncthreads();

    const int v = blockIdx.x * 128 + t;
    if (v >= Vn) return;

    const ulonglong2* Wv = (const ulonglong2*)(W + (size_t)v * Dn);
    ull acc[32];
#pragma unroll
    for (int b = 0; b < 32; b++) acc[b] = 0ull;

#pragma unroll 1
    for (int d4 = 0; d4 < Dn / 4; d4++) {
        ulonglong2 w2 = Wv[d4];            // (w0,w1) (w2,w3)
#pragma unroll
        for (int b = 0; b < 32; b++) {
            ulonglong2 u2 = u_sh[b * 32 + d4];   // broadcast across warp
            acc[b] = fma2(w2.x, u2.x, acc[b]);
            acc[b] = fma2(w2.y, u2.y, acc[b]);
        }
    }
    const float bv = bias[v];
#pragma unroll
    for (int b = 0; b < 32; b++) {
        float2 p = unpack2(acc[b]);
        out[(size_t)(bh * 32 + b) * Vn + v] = (p.x + p.y) + bv;
    }
}

// ---------------------------------------------------------------------------
extern "C" void kernel_launch(void* const* d_in, const int* in_sizes, int n_in,
                              void* d_out, int out_size)
{
    const int*   story    = (const int*)d_in[0];
    const int*   question = (const int*)d_in[1];
    const float* A0       = (const float*)d_in[2];
    const float* C0       = (const float*)d_in[3];
    const float* C1       = (const float*)d_in[4];
    const float* C2       = (const float*)d_in[5];
    const float* Bemb     = (const float*)d_in[6];
    const float* TA       = (const float*)d_in[7];
    const float* TC       = (const float*)d_in[8];
    const float* W        = (const float*)d_in[9];
    const float* bias     = (const float*)d_in[10];
    float* out = (float*)d_out;

    embed_story_kernel<<<dim3(Bn * Mn, 4), 128>>>(story, A0, C0, C1, C2);
    hops_kernel<<<Bn, 1024>>>(question, Bemb, TA, TC);
    logits_kernel<<<dim3((Vn + 127) / 128, 2), 128>>>(W, bias, out);
}

// round 7
// speedup vs baseline: 1.1781x; 1.1781x over previous
#include <cuda_runtime.h>

#define Bn 64
#define Mn 200
#define Sn 50
#define Qn 20
#define Dn 128
#define Vn 50000
#define HOPSn 3
#define NEG_INF -1e9f

typedef unsigned long long ull;

// ---- packed fp32x2 helpers (sm_103a FFMA2 via PTX) ----
__device__ __forceinline__ ull pack2(float lo, float hi) {
    ull r; asm("mov.b64 %0, {%1, %2};" : "=l"(r) : "f"(lo), "f"(hi)); return r;
}
__device__ __forceinline__ float2 unpack2(ull v) {
    float2 f; asm("mov.b64 {%0, %1}, %2;" : "=f"(f.x), "=f"(f.y) : "l"(v)); return f;
}
__device__ __forceinline__ ull fma2(ull a, ull b, ull c) {
    ull d; asm("fma.rn.f32x2 %0, %1, %2, %3;" : "=l"(d) : "l"(a), "l"(b), "l"(c)); return d;
}

// Scratch (static __device__ globals: allowed; no runtime allocation)
__device__ float g_emb[4][Bn * Mn][Dn];   // embeddings of A0, C0, C1, C2  (~26 MB)
__device__ float g_u[Bn][Dn];             // controller state after hops
__device__ int   g_nonpad[Bn * Mn];       // mem_nonpad mask

// ---------------------------------------------------------------------------
// Kernel 1: story embedding gather, FFMA2 two-accumulator version.
//  grid = (Bn*Mn, 4): y = table (L2 phase locality, proven R4).
//  Algebra: emb[d] = sum_s a_s*E[w_s,d] + c_d * sum_s b_s*E[w_s,d]
//  -> two packed accumulators, NO smem weight loads (R5's mistake), weights
//  computed in registers; combine with c_d once at the end.
// ---------------------------------------------------------------------------
__global__ void __launch_bounds__(128) embed_story_kernel(
    const int* __restrict__ story,
    const float* __restrict__ T0, const float* __restrict__ T1,
    const float* __restrict__ T2, const float* __restrict__ T3)
{
    __shared__ int    idx[Sn];
    __shared__ float4 part[4][32];
    const int bm   = blockIdx.x;
    const int tb   = blockIdx.y;
    const int t    = threadIdx.x;
    const int warp = t >> 5;
    const int lane = t & 31;

    if (t < Sn) idx[t] = story[bm * Sn + t];
    __syncthreads();
    if (tb == 0) {
        int np = __syncthreads_or((t < Sn) && (idx[t] != 0));
        if (t == 0) g_nonpad[bm] = np;
    }

    const ulonglong2* tab = (const ulonglong2*)(tb == 0 ? T0 : tb == 1 ? T1
                                                : tb == 2 ? T2 : T3);
    const float cb = (float)(4 * lane) * (1.0f / Dn);
    const ull cxy = pack2(cb + 1.0f / Dn, cb + 2.0f / Dn);
    const ull czw = pack2(cb + 3.0f / Dn, cb + 4.0f / Dn);

    ull aAxy = 0ull, aAzw = 0ull;   // sum a_s * r
    ull aBxy = 0ull, aBzw = 0ull;   // sum b_s * r

#define ROW_STEP(S_, R_)                                            \
    {                                                               \
        float j_  = (float)((S_) + 1);                              \
        float a_  = 1.0f - j_ * (1.0f / Sn);                        \
        float b_  = 2.0f * j_ * (1.0f / Sn) - 1.0f;                 \
        ull a2_ = pack2(a_, a_);                                    \
        ull b2_ = pack2(b_, b_);                                    \
        aAxy = fma2(a2_, (R_).x, aAxy);                             \
        aAzw = fma2(a2_, (R_).y, aAzw);                             \
        aBxy = fma2(b2_, (R_).x, aBxy);                             \
        aBzw = fma2(b2_, (R_).y, aBzw);                             \
    }

    const int start = (Sn * warp) >> 2;        // {0,12,25,37}
    const int end   = (Sn * (warp + 1)) >> 2;  // {12,25,37,50}
    int s = start;
    for (; s + 4 <= end; s += 4) {
        int w0 = idx[s], w1 = idx[s + 1], w2i = idx[s + 2], w3 = idx[s + 3];
        ulonglong2 r0 = tab[w0  * 32 + lane];
        ulonglong2 r1 = tab[w1  * 32 + lane];
        ulonglong2 r2 = tab[w2i * 32 + lane];
        ulonglong2 r3 = tab[w3  * 32 + lane];
        ROW_STEP(s,     r0);
        ROW_STEP(s + 1, r1);
        ROW_STEP(s + 2, r2);
        ROW_STEP(s + 3, r3);
    }
    for (; s < end; s++) {
        ulonglong2 r = tab[idx[s] * 32 + lane];
        ROW_STEP(s, r);
    }
#undef ROW_STEP

    // combine: res = accA + c * accB
    ull rxy = fma2(cxy, aBxy, aAxy);
    ull rzw = fma2(czw, aBzw, aAzw);
    float2 fxy = unpack2(rxy), fzw = unpack2(rzw);
    part[warp][lane] = make_float4(fxy.x, fxy.y, fzw.x, fzw.y);
    __syncthreads();
    if (warp == 0) {
        float4 a0 = part[0][lane], a1 = part[1][lane];
        float4 a2 = part[2][lane], a3 = part[3][lane];
        float4 r;
        r.x = (a0.x + a1.x) + (a2.x + a3.x);
        r.y = (a0.y + a1.y) + (a2.y + a3.y);
        r.z = (a0.z + a1.z) + (a2.z + a3.z);
        r.w = (a0.w + a1.w) + (a2.w + a3.w);
        ((float4*)g_emb[tb][bm])[lane] = r;
    }
}

// ---------------------------------------------------------------------------
// Kernel 2: query embed + 3 hops (exact R4 version, proven at 141.2us total).
// ---------------------------------------------------------------------------
__global__ void __launch_bounds__(1024) hops_kernel(
    const int* __restrict__ question, const float* __restrict__ Bemb,
    const float* __restrict__ TA, const float* __restrict__ TC)
{
    __shared__ float u_sh[Dn];
    __shared__ float sc[Mn];
    __shared__ float scp[Mn][33];        // padded: conflict-free transpose
    __shared__ float partial[8][Dn];
    __shared__ float red[32];
    __shared__ float s_max, s_sum;
    __shared__ int   qidx[Qn];
    __shared__ float qa[Qn], qb[Qn];

    const int b    = blockIdx.x;
    const int t    = threadIdx.x;
    const int warp = t >> 5;
    const int lane = t & 31;

    // ---- query embedding u^1 ----
    if (t < Qn) {
        int w = question[b * Qn + t];
        qidx[t] = w;
        float j = (float)(t + 1);
        qa[t] = 1.0f - j * (1.0f / Qn);
        qb[t] = 2.0f * j * (1.0f / Qn) - 1.0f;
    }
    __syncthreads();
    if (t < Dn) {
        const float cd = (float)(t + 1) * (1.0f / Dn);
        float acc = 0.f;
#pragma unroll
        for (int q = 0; q < Qn; q++) {
            float wgt = fmaf(qb[q], cd, qa[q]);
            acc = fmaf(wgt, Bemb[qidx[q] * Dn + t], acc);
        }
        u_sh[t] = acc;
    }
    __syncthreads();

    for (int k = 0; k < HOPSn; k++) {
        const float4* embA = (const float4*)g_emb[k];
        const float*  embC = (const float*)g_emb[k + 1];

        // ---- per-lane score partials (no shfl): warp covers m stride 32 ----
        float4 uu = ((const float4*)u_sh)[lane];
#pragma unroll 2
        for (int m = warp; m < Mn; m += 32) {
            float4 e  = embA[(b * Mn + m) * (Dn / 4) + lane];
            float4 ta = ((const float4*)TA)[m * (Dn / 4) + lane];
            float p = (e.x + ta.x) * uu.x + (e.y + ta.y) * uu.y
                    + (e.z + ta.z) * uu.z + (e.w + ta.w) * uu.w;
            scp[m][lane] = p;
        }
        __syncthreads();

        // ---- reduce 32 partials per m (4-way split accumulators) ----
        float lm = -3e38f;
        if (t < Mn) {
            float p0 = 0.f, p1 = 0.f, p2 = 0.f, p3 = 0.f;
#pragma unroll
            for (int i = 0; i < 32; i += 4) {
                p0 += scp[t][i];
                p1 += scp[t][i + 1];
                p2 += scp[t][i + 2];
                p3 += scp[t][i + 3];
            }
            float p = (p0 + p1) + (p2 + p3);
            p = g_nonpad[b * Mn + t] ? p : NEG_INF;
            sc[t] = p;
            lm = p;
        }
        // ---- softmax max ----
#pragma unroll
        for (int off = 16; off; off >>= 1)
            lm = fmaxf(lm, __shfl_down_sync(0xffffffffu, lm, off));
        if (lane == 0) red[warp] = lm;
        __syncthreads();
        if (warp == 0) {
            float v = red[lane];
#pragma unroll
            for (int off = 16; off; off >>= 1)
                v = fmaxf(v, __shfl_down_sync(0xffffffffu, v, off));
            if (lane == 0) s_max = v;
        }
        __syncthreads();
        // ---- exp + sum ----
        float e = 0.f;
        if (t < Mn) {
            e = __expf(sc[t] - s_max);
            sc[t] = e;
        }
#pragma unroll
        for (int off = 16; off; off >>= 1)
            e += __shfl_down_sync(0xffffffffu, e, off);
        if (lane == 0) red[warp] = e;
        __syncthreads();
        if (warp == 0) {
            float v = red[lane];
#pragma unroll
            for (int off = 16; off; off >>= 1)
                v += __shfl_down_sync(0xffffffffu, v, off);
            if (lane == 0) s_sum = v;
        }
        __syncthreads();
        const float inv = 1.0f / s_sum;

        // ---- o[d] = sum_m p[m]*(c_k[m,d]+TC[m,d]) : 8 groups x 128 ----
        const int g = t >> 7;     // group 0..7
        const int d = t & 127;    // dim
        float o = 0.f;
#pragma unroll
        for (int mi = 0; mi < Mn / 8; mi++) {
            int m = g + mi * 8;
            float c = embC[(b * Mn + m) * Dn + d] + TC[m * Dn + d];
            o = fmaf(sc[m], c, o);
        }
        partial[g][d] = o;
        __syncthreads();
        if (t < Dn) {
            float s2 = 0.f;
#pragma unroll
            for (int g2 = 0; g2 < 8; g2++) s2 += partial[g2][t];
            u_sh[t] += s2 * inv;
        }
        __syncthreads();
    }
    if (t < Dn) g_u[b][t] = u_sh[t];
}

// ---------------------------------------------------------------------------
// Kernel 3: logits = u @ W^T + bias (exact R4 version).
// ---------------------------------------------------------------------------
__global__ void __launch_bounds__(128) logits_kernel(
    const float* __restrict__ W, const float* __restrict__ bias,
    float* __restrict__ out)
{
    __shared__ float4 u_sh[Bn * (Dn / 4)];   // 32 KB
    const int t = threadIdx.x;
    const float4* gu4 = (const float4*)g_u;
#pragma unroll
    for (int i = 0; i < (Bn * Dn / 4) / 128; i++)
        u_sh[t + i * 128] = gu4[t + i * 128];
    __syncthreads();

    const int v = blockIdx.x * 128 + t;
    if (v >= Vn) return;

    const float4* Wv = (const float4*)(W + (size_t)v * Dn);
    float acc[Bn];
#pragma unroll
    for (int b = 0; b < Bn; b++) acc[b] = 0.f;

#pragma unroll 1
    for (int d4 = 0; d4 < Dn / 4; d4++) {
        float4 w4 = Wv[d4];
#pragma unroll
        for (int b = 0; b < Bn; b++) {
            float4 uu = u_sh[b * (Dn / 4) + d4];   // broadcast across warp
            acc[b] = fmaf(w4.x, uu.x, acc[b]);
            acc[b] = fmaf(w4.y, uu.y, acc[b]);
            acc[b] = fmaf(w4.z, uu.z, acc[b]);
            acc[b] = fmaf(w4.w, uu.w, acc[b]);
        }
    }
    const float bv = bias[v];
#pragma unroll
    for (int b = 0; b < Bn; b++)
        out[(size_t)b * Vn + v] = acc[b] + bv;
}

// ---------------------------------------------------------------------------
extern "C" void kernel_launch(void* const* d_in, const int* in_sizes, int n_in,
                              void* d_out, int out_size)
{
    const int*   story    = (const int*)d_in[0];
    const int*   question = (const int*)d_in[1];
    const float* A0       = (const float*)d_in[2];
    const float* C0       = (const float*)d_in[3];
    const float* C1       = (const float*)d_in[4];
    const float* C2       = (const float*)d_in[5];
    const float* Bemb     = (const float*)d_in[6];
    const float* TA       = (const float*)d_in[7];
    const float* TC       = (const float*)d_in[8];
    const float* W        = (const float*)d_in[9];
    const float* bias     = (const float*)d_in[10];
    float* out = (float*)d_out;

    embed_story_kernel<<<dim3(Bn * Mn, 4), 128>>>(story, A0, C0, C1, C2);
    hops_kernel<<<Bn, 1024>>>(question, Bemb, TA, TC);
    logits_kernel<<<(Vn + 127) / 128, 128>>>(W, bias, out);
}